// round 3
// baseline (speedup 1.0000x reference)
#include <cuda_runtime.h>

#define NPIX 1024
#define NVCH 64
#define R 3
#define TW 128
#define TH 32
#define SINW 136   // 134 used + 2 pad, keeps rows 16B-aligned

__device__ float g_cube[(size_t)NVCH * NPIX * NPIX];   // 256 MB scratch
__device__ float g_g1d[8];

// ---------------------------------------------------------------- zero cube
__global__ __launch_bounds__(256) void zero_k() {
    float4* p = reinterpret_cast<float4*>(g_cube);
    const int n4 = NVCH * NPIX * NPIX / 4;
    float4 z = make_float4(0.f, 0.f, 0.f, 0.f);
    for (int i = blockIdx.x * 256 + threadIdx.x; i < n4; i += gridDim.x * 256)
        p[i] = z;
}

// ------------------------------------------------- recover separable 1D taps
// kernel2d[i][j] = g[i]*g[j] with sum(g)=1  =>  row-sum = g[i] (to fp32 eps)
__global__ void prep_k(const float* __restrict__ k2d) {
    int k = threadIdx.x;
    if (k < 7) {
        float s = 0.f;
        #pragma unroll
        for (int j = 0; j < 7; j++) s += k2d[k * 7 + j];
        g_g1d[k] = s;
    }
}

// ---------------------------------------------------------------- scatter
__global__ __launch_bounds__(256) void scatter_k(
    const float* __restrict__ pos,   // (M,2) interleaved ra,dec
    const float* __restrict__ vel,
    const float* __restrict__ flx,
    const float* __restrict__ vax,
    int M)
{
    int i = blockIdx.x * 256 + threadIdx.x;
    if (i >= M) return;

    float2 p = reinterpret_cast<const float2*>(pos)[i];
    float v  = vel[i];
    float f  = flx[i];

    float vel0 = __ldg(&vax[0]);
    float dv   = __fsub_rn(__ldg(&vax[1]), vel0);

    const float FOVH = 51.15f;      // f32(0.5*(1024-1)*0.1)
    // XLA rewrites x / 0.1f -> x * 10.0f (reciprocal round-trips exactly).
    // Replicate: IEEE add then IEEE mul by 10.0f, then floor.
    int ix = (int)floorf(__fmul_rn(__fadd_rn(p.x, FOVH), 10.0f));
    int iy = (int)floorf(__fmul_rn(__fadd_rn(p.y, FOVH), 10.0f));
    // dv is a runtime value -> XLA keeps a true division; match with div.rn.
    int iv = (int)floorf(__fdiv_rn(__fsub_rn(v, vel0), dv));

    // mask: margin = 7//2 + 1 = 4
    if ((unsigned)(ix + 4) >= (unsigned)(NPIX + 8)) return;
    if ((unsigned)(iy + 4) >= (unsigned)(NPIX + 8)) return;
    if ((unsigned)iv >= (unsigned)NVCH) return;

    // JAX scatter mode="drop": drop on FLAT index bounds (margin pixels with
    // e.g. ix=-1 wrap into the previous row, matching flat-index arithmetic).
    int flat = (iv * NPIX + iy) * NPIX + ix;
    if ((unsigned)flat < (unsigned)(NVCH * NPIX * NPIX))
        atomicAdd(&g_cube[flat], f);
}

// --------------------------------------- fused separable 7x7 conv, per tile
__global__ __launch_bounds__(256) void conv_k(float* __restrict__ out) {
    __shared__ float s_in[TH + 6][SINW];
    __shared__ float s_h [TH + 6][TW];
    __shared__ float s_g[8];

    const int tid = threadIdx.x;
    const int x0 = blockIdx.x * TW;
    const int y0 = blockIdx.y * TH;
    const int ch = blockIdx.z;

    const float* __restrict__ cube = g_cube + (size_t)ch * NPIX * NPIX;
    float* __restrict__ outc = out + (size_t)ch * NPIX * NPIX;

    if (tid < 7) s_g[tid] = g_g1d[tid];

    // ---- load (TH+6) x (TW+6) input tile with zero halo
    for (int i = tid; i < (TH + 6) * (TW + 6); i += 256) {
        int r = i / (TW + 6);
        int c = i - r * (TW + 6);
        int gy = y0 + r - R;
        int gx = x0 + c - R;
        float v = 0.f;
        if ((unsigned)gx < (unsigned)NPIX && (unsigned)gy < (unsigned)NPIX)
            v = cube[gy * NPIX + gx];
        s_in[r][c] = v;
    }
    __syncthreads();

    const float g0 = s_g[0], g1 = s_g[1], g2 = s_g[2], g3 = s_g[3],
                g4 = s_g[4], g5 = s_g[5], g6 = s_g[6];

    // ---- horizontal pass: each unit = 4 consecutive output cols (float4 LDS/STS)
    for (int u = tid; u < (TH + 6) * (TW / 4); u += 256) {
        int r  = u / (TW / 4);
        int cq = (u - r * (TW / 4)) * 4;
        float4 v0 = *reinterpret_cast<const float4*>(&s_in[r][cq]);
        float4 v1 = *reinterpret_cast<const float4*>(&s_in[r][cq + 4]);
        float4 v2 = *reinterpret_cast<const float4*>(&s_in[r][cq + 8]);
        float a0 = v0.x, a1 = v0.y, a2 = v0.z, a3 = v0.w;
        float a4 = v1.x, a5 = v1.y, a6 = v1.z, a7 = v1.w;
        float a8 = v2.x, a9 = v2.y;
        float4 s;
        s.x = a0*g0 + a1*g1 + a2*g2 + a3*g3 + a4*g4 + a5*g5 + a6*g6;
        s.y = a1*g0 + a2*g1 + a3*g2 + a4*g3 + a5*g4 + a6*g5 + a7*g6;
        s.z = a2*g0 + a3*g1 + a4*g2 + a5*g3 + a6*g4 + a7*g5 + a8*g6;
        s.w = a3*g0 + a4*g1 + a5*g2 + a6*g3 + a7*g4 + a8*g5 + a9*g6;
        *reinterpret_cast<float4*>(&s_h[r][cq]) = s;
    }
    __syncthreads();

    // ---- vertical pass: each unit = 4 consecutive output rows, 1 col
    for (int u = tid; u < (TH / 4) * TW; u += 256) {
        int rq = (u / TW) * 4;
        int c  = u - (u / TW) * TW;
        float a0 = s_h[rq + 0][c], a1 = s_h[rq + 1][c], a2 = s_h[rq + 2][c];
        float a3 = s_h[rq + 3][c], a4 = s_h[rq + 4][c], a5 = s_h[rq + 5][c];
        float a6 = s_h[rq + 6][c], a7 = s_h[rq + 7][c], a8 = s_h[rq + 8][c];
        float a9 = s_h[rq + 9][c];
        float o0 = a0*g0 + a1*g1 + a2*g2 + a3*g3 + a4*g4 + a5*g5 + a6*g6;
        float o1 = a1*g0 + a2*g1 + a3*g2 + a4*g3 + a5*g4 + a6*g5 + a7*g6;
        float o2 = a2*g0 + a3*g1 + a4*g2 + a5*g3 + a6*g4 + a7*g5 + a8*g6;
        float o3 = a3*g0 + a4*g1 + a5*g2 + a6*g3 + a7*g4 + a8*g5 + a9*g6;
        size_t base = (size_t)(y0 + rq) * NPIX + x0 + c;
        outc[base]            = o0;
        outc[base + NPIX]     = o1;
        outc[base + 2 * NPIX] = o2;
        outc[base + 3 * NPIX] = o3;
    }
}

extern "C" void kernel_launch(void* const* d_in, const int* in_sizes, int n_in,
                              void* d_out, int out_size) {
    const float* pos = (const float*)d_in[0];   // pos_img (M,2)
    const float* vel = (const float*)d_in[1];   // vel_chan (M,)
    const float* flx = (const float*)d_in[2];   // flux (M,)
    const float* vax = (const float*)d_in[3];   // vel_axis (64,)
    const float* k2d = (const float*)d_in[4];   // kernel2d (49,)
    float* out = (float*)d_out;

    int M = in_sizes[1];

    zero_k<<<4736, 256>>>();
    prep_k<<<1, 32>>>(k2d);
    scatter_k<<<(M + 255) / 256, 256>>>(pos, vel, flx, vax, M);

    dim3 grid(NPIX / TW, NPIX / TH, NVCH);
    conv_k<<<grid, 256>>>(out);
}

// round 5
// speedup vs baseline: 1.6274x; 1.6274x over previous
#include <cuda_runtime.h>

#define NPIX 1024
#define NVCH 64
#define RB 128          // output rows per conv block

__device__ float g_cube[(size_t)NVCH * NPIX * NPIX];   // 256 MB scratch
__device__ float g_g1d[8];

// ---------------------------------------------------------------- zero cube
__global__ __launch_bounds__(256) void zero_k() {
    float4* p = reinterpret_cast<float4*>(g_cube);
    const int n4 = NVCH * NPIX * NPIX / 4;
    float4 z = make_float4(0.f, 0.f, 0.f, 0.f);
    for (int i = blockIdx.x * 256 + threadIdx.x; i < n4; i += gridDim.x * 256)
        p[i] = z;
}

// ------------------------------------------------- recover separable 1D taps
// kernel2d[i][j] = g[i]*g[j] with sum(g)=1  =>  row-sum = g[i] (to fp32 eps)
__global__ void prep_k(const float* __restrict__ k2d) {
    int k = threadIdx.x;
    if (k < 7) {
        float s = 0.f;
        #pragma unroll
        for (int j = 0; j < 7; j++) s += k2d[k * 7 + j];
        g_g1d[k] = s;
    }
}

// ---------------------------------------------------------------- scatter
__global__ __launch_bounds__(256) void scatter_k(
    const float* __restrict__ pos,   // (M,2) interleaved ra,dec
    const float* __restrict__ vel,
    const float* __restrict__ flx,
    const float* __restrict__ vax,
    int M)
{
    int i = blockIdx.x * 256 + threadIdx.x;
    if (i >= M) return;

    float2 p = reinterpret_cast<const float2*>(pos)[i];
    float v  = vel[i];
    float f  = flx[i];

    float vel0 = __ldg(&vax[0]);
    float dv   = __fsub_rn(__ldg(&vax[1]), vel0);

    const float FOVH = 51.15f;      // f32(0.5*(1024-1)*0.1)
    // XLA rewrites x / 0.1f -> x * 10.0f (reciprocal round-trips exactly).
    int ix = (int)floorf(__fmul_rn(__fadd_rn(p.x, FOVH), 10.0f));
    int iy = (int)floorf(__fmul_rn(__fadd_rn(p.y, FOVH), 10.0f));
    // dv is a runtime value -> XLA keeps a true division; match with div.rn.
    int iv = (int)floorf(__fdiv_rn(__fsub_rn(v, vel0), dv));

    // mask: margin = 7//2 + 1 = 4
    if ((unsigned)(ix + 4) >= (unsigned)(NPIX + 8)) return;
    if ((unsigned)(iy + 4) >= (unsigned)(NPIX + 8)) return;
    if ((unsigned)iv >= (unsigned)NVCH) return;

    // JAX scatter mode="drop": drop on FLAT index bounds (margin pixels with
    // e.g. ix=-1 wrap into the previous row, matching flat-index arithmetic).
    int flat = (iv * NPIX + iy) * NPIX + ix;
    if ((unsigned)flat < (unsigned)(NVCH * NPIX * NPIX))
        atomicAdd(&g_cube[flat], f);
}

// ----------------- register-streaming separable 7x7 conv (no smem, no bar)
// lane owns 4 cols; warp owns 128-col strip; block = 8 warps = full width.
// 7-row rolling ring of horizontal results lives in registers (unroll x7).
// NOTE: VERT takes the ring index explicitly (JJ) so STEP's parameter J is
// substituted to a literal BEFORE VERT expands (fixes R4 macro-scope bug).

#define VERT(JJ, comp)                                                        \
    (g0*h[((JJ)+1)%7].comp + g1*h[((JJ)+2)%7].comp + g2*h[((JJ)+3)%7].comp +  \
     g3*h[((JJ)+4)%7].comp + g4*h[((JJ)+5)%7].comp + g5*h[((JJ)+6)%7].comp +  \
     g6*h[(JJ)%7].comp)

#define STEP(J, IT)                                                           \
{                                                                             \
    const int it = (IT);                                                      \
    const int yh = y0 - 3 + it;                                               \
    float4 a  = make_float4(0.f, 0.f, 0.f, 0.f);                              \
    float4 hl = a, hr = a;                                                    \
    if ((unsigned)yh < (unsigned)NPIX) {                                      \
        const float* rp = cube + (size_t)yh * NPIX;                           \
        a = *(const float4*)(rp + c);                                         \
        if (lane == 0  && c >= 4)         hl = *(const float4*)(rp + c - 4);  \
        if (lane == 31 && c + 7 < NPIX)   hr = *(const float4*)(rp + c + 4);  \
    }                                                                         \
    float lm1 = __shfl_up_sync(0xffffffffu, a.w, 1);                          \
    float lm2 = __shfl_up_sync(0xffffffffu, a.z, 1);                          \
    float lm3 = __shfl_up_sync(0xffffffffu, a.y, 1);                          \
    if (lane == 0)  { lm1 = hl.w; lm2 = hl.z; lm3 = hl.y; }                   \
    float rq1 = __shfl_down_sync(0xffffffffu, a.x, 1);                        \
    float rq2 = __shfl_down_sync(0xffffffffu, a.y, 1);                        \
    float rq3 = __shfl_down_sync(0xffffffffu, a.z, 1);                        \
    if (lane == 31) { rq1 = hr.x; rq2 = hr.y; rq3 = hr.z; }                   \
    float4 hx;                                                                \
    hx.x = lm3*g0 + lm2*g1 + lm1*g2 + a.x*g3 + a.y*g4 + a.z*g5 + a.w*g6;      \
    hx.y = lm2*g0 + lm1*g1 + a.x*g2 + a.y*g3 + a.z*g4 + a.w*g5 + rq1*g6;      \
    hx.z = lm1*g0 + a.x*g1 + a.y*g2 + a.z*g3 + a.w*g4 + rq1*g5 + rq2*g6;      \
    hx.w = a.x*g0 + a.y*g1 + a.z*g2 + a.w*g3 + rq1*g4 + rq2*g5 + rq3*g6;      \
    h[(J)%7] = hx;                                                            \
    if (it >= 6) {                                                            \
        float4 o;                                                             \
        o.x = VERT(J, x); o.y = VERT(J, y);                                   \
        o.z = VERT(J, z); o.w = VERT(J, w);                                   \
        *(float4*)(outc + (size_t)(yh - 3) * NPIX + c) = o;                   \
    }                                                                         \
}

__global__ __launch_bounds__(256) void conv_k(float* __restrict__ out) {
    const int lane = threadIdx.x & 31;
    const int wrp  = threadIdx.x >> 5;
    const int ch   = blockIdx.y;
    const int y0   = blockIdx.x * RB;
    const int c    = (wrp << 7) + (lane << 2);      // column base (x4 cols)

    const float* __restrict__ cube = g_cube + (size_t)ch * (NPIX * NPIX);
    float* __restrict__ outc = out + (size_t)ch * (NPIX * NPIX);

    const float g0 = g_g1d[0], g1 = g_g1d[1], g2 = g_g1d[2], g3 = g_g1d[3],
                g4 = g_g1d[4], g5 = g_g1d[5], g6 = g_g1d[6];

    float4 h[7];

    // RB+6 = 134 producer rows: 19 chunks of 7 (it 0..132) + tail (it 133)
    #pragma unroll 1
    for (int base = 0; base < RB + 5; base += 7) {
        STEP(0, base + 0)
        STEP(1, base + 1)
        STEP(2, base + 2)
        STEP(3, base + 3)
        STEP(4, base + 4)
        STEP(5, base + 5)
        STEP(6, base + 6)
    }
    STEP(0, RB + 5)     // it = 133, slot 133%7 == 0
}

extern "C" void kernel_launch(void* const* d_in, const int* in_sizes, int n_in,
                              void* d_out, int out_size) {
    const float* pos = (const float*)d_in[0];   // pos_img (M,2)
    const float* vel = (const float*)d_in[1];   // vel_chan (M,)
    const float* flx = (const float*)d_in[2];   // flux (M,)
    const float* vax = (const float*)d_in[3];   // vel_axis (64,)
    const float* k2d = (const float*)d_in[4];   // kernel2d (49,)
    float* out = (float*)d_out;

    int M = in_sizes[1];

    zero_k<<<4736, 256>>>();
    prep_k<<<1, 32>>>(k2d);
    scatter_k<<<(M + 255) / 256, 256>>>(pos, vel, flx, vax, M);

    dim3 grid(NPIX / RB, NVCH);
    conv_k<<<grid, 256>>>(out);
}